// round 8
// baseline (speedup 1.0000x reference)
#include <cuda_runtime.h>
#include <cuda_bf16.h>
#include <math.h>

// Problem constants
#define BB   8
#define DIM  128
#define HH   64
#define WW   64
#define HW   4096
#define KK   7
#define GG   8
#define GC   16
#define C1   32
#define C2   392
#define NPIX 32768

// -------- scratch (device globals) --------
__device__ float    g_t[BB * C1 * HW];        // conv1+bn+relu, NCHW fp32 (4 MB)
__device__ float    g_y[NPIX * DIM];          // involution out, NHWC fp32 (17 MB)
__device__ unsigned g_yn[NPIX * 64];          // LN out, bf16 pairs along c, [px][c/2] (8 MB)
__device__ unsigned g_hb[NPIX * 128];         // pw1+gelu out, bf16 pairs along f, [px][f/2] (16 MB)

// -------- helpers --------
__device__ __forceinline__ unsigned packbf(float lo, float hi) {
    unsigned r; asm("cvt.rn.bf16x2.f32 %0, %1, %2;" : "=r"(r) : "f"(hi), "f"(lo)); return r;
}
__device__ __forceinline__ void mma16(float* c, unsigned a0, unsigned a1,
                                      unsigned a2, unsigned a3,
                                      unsigned b0, unsigned b1) {
    asm volatile(
        "mma.sync.aligned.m16n8k16.row.col.f32.bf16.bf16.f32 "
        "{%0,%1,%2,%3}, {%4,%5,%6,%7}, {%8,%9}, {%0,%1,%2,%3};\n"
        : "+f"(c[0]), "+f"(c[1]), "+f"(c[2]), "+f"(c[3])
        : "r"(a0), "r"(a1), "r"(a2), "r"(a3), "r"(b0), "r"(b1));
}
// tanh-form GELU, branch-free (~9 instr). |z| <~1.3 in this net → abs err <2e-4.
__device__ __forceinline__ float gelu_fast(float z) {
    float u = z * (0.7978845608f + 0.0356774081f * z * z);
    float e = __expf(-2.f * u);
    return __fdividef(z, 1.f + e);
}

// =====================================================================
// K1: t = relu(bn(conv1(x)))  — bf16 MMA, M=32, N=128px, K=128
// =====================================================================
__global__ __launch_bounds__(256) void k1_conv1(
    const float* __restrict__ x,  const float* __restrict__ w1,
    const float* __restrict__ b1, const float* __restrict__ bng,
    const float* __restrict__ bnb, const float* __restrict__ bnm,
    const float* __restrict__ bnv) {
    extern __shared__ unsigned smu[];
    unsigned* wAu = smu;                 // 32*68
    unsigned* xsu = smu + 32 * 68;       // 64*136
    float* bs = (float*)(xsu + 64 * 136);
    float* ss = bs + 32;
    int tid = threadIdx.x;

    if (tid < 32) {
        float sc = bng[tid] * rsqrtf(bnv[tid] + 1e-5f);
        ss[tid] = sc;
        bs[tid] = b1[tid] * sc + bnb[tid] - bnm[tid] * sc;
    }
    __syncthreads();
    for (int i = tid; i < 32 * 64; i += 256) {
        int o = i >> 6, c2 = i & 63;
        float sc = ss[o];
        wAu[o * 68 + c2] = packbf(w1[o * 128 + 2 * c2] * sc, w1[o * 128 + 2 * c2 + 1] * sc);
    }
    int pb = blockIdx.x * 128, b = pb >> 12, pin = pb & 4095;
    const float* xb = x + b * DIM * HW + pin;
    for (int i = tid; i < 64 * 128; i += 256) {
        int c2 = i >> 7, p = i & 127;
        xsu[c2 * 136 + p] = packbf(xb[(2 * c2) * HW + p], xb[(2 * c2 + 1) * HW + p]);
    }
    __syncthreads();

    int wid = tid >> 5, lane = tid & 31, gid = lane >> 2, ctid = lane & 3;
    int m = wid & 1, ng = wid >> 1;
    int px0 = ng * 32;
    float acc[4][4];
#pragma unroll
    for (int a = 0; a < 4; a++)
#pragma unroll
        for (int q = 0; q < 4; q++) acc[a][q] = 0.f;

#pragma unroll
    for (int s = 0; s < 8; s++) {
        const unsigned* ap = wAu + (m * 16 + gid) * 68 + s * 8 + ctid;
        unsigned a0 = ap[0], a1 = ap[8 * 68], a2 = ap[4], a3 = ap[8 * 68 + 4];
#pragma unroll
        for (int nt = 0; nt < 4; nt++) {
            int pxn = px0 + nt * 8 + gid;
            unsigned b0 = xsu[(s * 8 + ctid) * 136 + pxn];
            unsigned b1v = xsu[(s * 8 + ctid + 4) * 136 + pxn];
            mma16(acc[nt], a0, a1, a2, a3, b0, b1v);
        }
    }
    float* tb = g_t + b * C1 * HW + pin;
    int o0 = m * 16 + gid;
#pragma unroll
    for (int nt = 0; nt < 4; nt++) {
        int px = px0 + nt * 8 + 2 * ctid;
        float b0v = bs[o0], b1v = bs[o0 + 8];
        *(float2*)(tb + o0 * HW + px) =
            make_float2(fmaxf(acc[nt][0] + b0v, 0.f), fmaxf(acc[nt][1] + b0v, 0.f));
        *(float2*)(tb + (o0 + 8) * HW + px) =
            make_float2(fmaxf(acc[nt][2] + b1v, 0.f), fmaxf(acc[nt][3] + b1v, 0.f));
    }
}

// =====================================================================
// K23: fused conv2 + involution
// =====================================================================
#define XS_ROW 72
#define XS_CH  (14 * 72)
#define WGT_S  520
__global__ __launch_bounds__(256) void k23_conv2_inv(
    const float* __restrict__ x, const float* __restrict__ w2,
    const float* __restrict__ b2) {
    extern __shared__ float smf[];
    float* wgt = smf;
    float* xs  = smf + 49 * WGT_S;
    unsigned* tsu = (unsigned*)xs;
    unsigned* wAu = tsu + 16 * WGT_S;
    float* bsm = (float*)(wAu + 64 * 20);
    int tid = threadIdx.x;
    int h0 = blockIdx.x * 8;
    int g  = blockIdx.y;
    int b  = blockIdx.z;

    const float* tb = g_t + b * C1 * HW + h0 * 64;
    for (int i = tid; i < 16 * 512; i += 256) {
        int c2 = i >> 9, px = i & 511;
        tsu[c2 * WGT_S + px] = packbf(tb[(2 * c2) * HW + px], tb[(2 * c2 + 1) * HW + px]);
    }
    for (int i = tid; i < 64 * 16; i += 256) {
        int o = i >> 4, c2 = i & 15;
        float a0 = 0.f, a1 = 0.f;
        if (o < 49) {
            int go = g * 49 + o;
            a0 = w2[go * C1 + 2 * c2];
            a1 = w2[go * C1 + 2 * c2 + 1];
        }
        wAu[o * 20 + c2] = packbf(a0, a1);
    }
    if (tid < 64) bsm[tid] = (tid < 49) ? b2[g * 49 + tid] : 0.f;
    __syncthreads();

    int wid = tid >> 5, lane = tid & 31, gid = lane >> 2, ctid = lane & 3;
    int m = wid & 3, ng = wid >> 2;
    int orow = m * 16 + gid;
    float bb0 = bsm[orow], bb1 = bsm[orow + 8];
#pragma unroll
    for (int nh = 0; nh < 2; nh++) {
        float acc[16][4];
#pragma unroll
        for (int nt = 0; nt < 16; nt++)
#pragma unroll
            for (int q = 0; q < 4; q++) acc[nt][q] = 0.f;
#pragma unroll
        for (int s = 0; s < 2; s++) {
            const unsigned* ap = wAu + orow * 20 + s * 8 + ctid;
            unsigned a0 = ap[0], a1 = ap[8 * 20], a2 = ap[4], a3 = ap[8 * 20 + 4];
#pragma unroll
            for (int nt = 0; nt < 16; nt++) {
                int pxn = nh * 256 + ng * 128 + nt * 8 + gid;
                unsigned b0 = tsu[(s * 8 + ctid) * WGT_S + pxn];
                unsigned b1v = tsu[(s * 8 + ctid + 4) * WGT_S + pxn];
                mma16(acc[nt], a0, a1, a2, a3, b0, b1v);
            }
        }
#pragma unroll
        for (int nt = 0; nt < 16; nt++) {
            int px = nh * 256 + ng * 128 + nt * 8 + 2 * ctid;
            if (orow < 49)
                *(float2*)(wgt + orow * WGT_S + px) =
                    make_float2(acc[nt][0] + bb0, acc[nt][1] + bb0);
            if (orow + 8 < 49)
                *(float2*)(wgt + (orow + 8) * WGT_S + px) =
                    make_float2(acc[nt][2] + bb1, acc[nt][3] + bb1);
        }
    }
    __syncthreads();

    for (int i = tid; i < GC * XS_CH; i += 256) xs[i] = 0.f;
    __syncthreads();
    const float* xg = x + (b * DIM + g * GC) * HW;
    for (int idx = tid; idx < GC * 14 * 64; idx += 256) {
        int gc = idx / (14 * 64);
        int rem = idx - gc * (14 * 64);
        int rr = rem >> 6, ww = rem & 63;
        int hh = h0 - 3 + rr;
        if (hh >= 0 && hh < HH)
            xs[gc * XS_CH + rr * XS_ROW + ww + 3] = xg[gc * HW + hh * WW + ww];
    }
    __syncthreads();

    int gcH = tid & 1;
    int pxq = tid >> 1;
    int r = pxq >> 4, w0 = (pxq & 15) * 4;
    float acc[8][4];
#pragma unroll
    for (int gc8 = 0; gc8 < 8; gc8++)
#pragma unroll
        for (int l = 0; l < 4; l++) acc[gc8][l] = 0.f;

    const float* wp = wgt + r * 64 + w0;
#pragma unroll
    for (int i = 0; i < KK; i++) {
        float4 wv[KK];
#pragma unroll
        for (int j = 0; j < KK; j++)
            wv[j] = *(const float4*)(wp + (i * KK + j) * WGT_S);
#pragma unroll
        for (int gc8 = 0; gc8 < 8; gc8++) {
            int gc = gcH * 8 + gc8;
            const float* xrow = xs + gc * XS_CH + (r + i) * XS_ROW + w0;
            float4 xa = *(const float4*)(xrow);
            float4 xb4 = *(const float4*)(xrow + 4);
            float4 xc = *(const float4*)(xrow + 8);
            float xw[12] = {xa.x, xa.y, xa.z, xa.w, xb4.x, xb4.y, xb4.z, xb4.w,
                            xc.x, xc.y, xc.z, xc.w};
#pragma unroll
            for (int j = 0; j < KK; j++) {
                acc[gc8][0] += wv[j].x * xw[j];
                acc[gc8][1] += wv[j].y * xw[j + 1];
                acc[gc8][2] += wv[j].z * xw[j + 2];
                acc[gc8][3] += wv[j].w * xw[j + 3];
            }
        }
    }
#pragma unroll
    for (int l = 0; l < 4; l++) {
        float* yo = g_y + (b * HW + (h0 + r) * WW + w0 + l) * DIM + g * GC + gcH * 8;
        *(float4*)(yo)     = make_float4(acc[0][l], acc[1][l], acc[2][l], acc[3][l]);
        *(float4*)(yo + 4) = make_float4(acc[4][l], acc[5][l], acc[6][l], acc[7][l]);
    }
}

// =====================================================================
// K4LN: LayerNorm, warp per pixel. g_yn layout [px][c/2].
// =====================================================================
__global__ __launch_bounds__(256) void k4_ln(
    const float* __restrict__ lng_g, const float* __restrict__ lnb_g) {
    __shared__ float lng[128], lnb[128];
    int tid = threadIdx.x;
    if (tid < 128) { lng[tid] = lng_g[tid]; lnb[tid] = lnb_g[tid]; }
    __syncthreads();

    int warp = tid >> 5, lane = tid & 31;
    int p = blockIdx.x * 8 + warp;
    float4 v = *(const float4*)(g_y + p * DIM + lane * 4);
    float s = v.x + v.y + v.z + v.w;
    float q = v.x*v.x + v.y*v.y + v.z*v.z + v.w*v.w;
#pragma unroll
    for (int off = 16; off; off >>= 1) {
        s += __shfl_xor_sync(0xffffffffu, s, off);
        q += __shfl_xor_sync(0xffffffffu, q, off);
    }
    float mu = s * (1.f / 128.f);
    float var = q * (1.f / 128.f) - mu * mu;
    float rs = rsqrtf(var + 1e-6f);
    int c = lane * 4;
    float n0 = (v.x - mu) * rs * lng[c+0] + lnb[c+0];
    float n1 = (v.y - mu) * rs * lng[c+1] + lnb[c+1];
    float n2 = (v.z - mu) * rs * lng[c+2] + lnb[c+2];
    float n3 = (v.w - mu) * rs * lng[c+3] + lnb[c+3];
    g_yn[p * 64 + lane * 2]     = packbf(n0, n1);
    g_yn[p * 64 + lane * 2 + 1] = packbf(n2, n3);
}

// =====================================================================
// K4A: pw1 + fast GELU. M=64 f/block (of 256), N=128 px.
// grid (256, 4), block 256, 3 CTAs/SM.
// =====================================================================
#define OT_S 130
__global__ __launch_bounds__(256, 3) void k4a_pw1(
    const float* __restrict__ p1w, const float* __restrict__ p1b) {
    extern __shared__ unsigned smu[];
    unsigned* w1u = smu;                       // 64*68
    unsigned* ysu = smu + 64 * 68;             // 64*137
    float* b1s = (float*)(ysu + 64 * 137);     // 64
    float* outT = (float*)smu;                 // 64*130 (union)
    int tid = threadIdx.x;
    int f0 = blockIdx.y * 64;
    int pb = blockIdx.x * 128;

#pragma unroll
    for (int k = 0; k < 16; k++) {
        int i = tid + k * 256;
        int f = i >> 6, c2 = i & 63;
        float2 wv = *(const float2*)(p1w + (f0 + f) * 128 + 2 * c2);
        w1u[f * 68 + c2] = packbf(wv.x, wv.y);
    }
    if (tid < 64) b1s[tid] = p1b[f0 + tid];
#pragma unroll
    for (int k = 0; k < 32; k++) {
        int i = tid + k * 256;
        int p = i >> 6, c2 = i & 63;
        ysu[c2 * 137 + p] = g_yn[(pb + p) * 64 + c2];
    }
    __syncthreads();

    int wid = tid >> 5, lane = tid & 31, gid = lane >> 2, ctid = lane & 3;
    int m = wid & 3, ng = wid >> 2;
    float acc[8][4];
#pragma unroll
    for (int nt = 0; nt < 8; nt++)
#pragma unroll
        for (int q = 0; q < 4; q++) acc[nt][q] = 0.f;

#pragma unroll
    for (int s = 0; s < 8; s++) {
        const unsigned* ap = w1u + (m * 16 + gid) * 68 + s * 8 + ctid;
        unsigned a0 = ap[0], a1 = ap[8 * 68], a2 = ap[4], a3 = ap[8 * 68 + 4];
#pragma unroll
        for (int nt = 0; nt < 8; nt++) {
            int pxn = ng * 64 + nt * 8 + gid;
            unsigned b0 = ysu[(s * 8 + ctid) * 137 + pxn];
            unsigned b1v = ysu[(s * 8 + ctid + 4) * 137 + pxn];
            mma16(acc[nt], a0, a1, a2, a3, b0, b1v);
        }
    }
    __syncthreads();   // staging dead → outT

    int frow = m * 16 + gid;
    float bb0 = b1s[frow], bb1 = b1s[frow + 8];
#pragma unroll
    for (int nt = 0; nt < 8; nt++) {
        int px = ng * 64 + nt * 8 + 2 * ctid;
        *(float2*)(outT + frow * OT_S + px) =
            make_float2(gelu_fast(acc[nt][0] + bb0), gelu_fast(acc[nt][1] + bb0));
        *(float2*)(outT + (frow + 8) * OT_S + px) =
            make_float2(gelu_fast(acc[nt][2] + bb1), gelu_fast(acc[nt][3] + bb1));
    }
    __syncthreads();

    // coalesced pack + store to g_hb [px][f/2]: 128 px × 32 f-pairs = 4096
    int fcol = f0 >> 1;
#pragma unroll
    for (int k = 0; k < 16; k++) {
        int i = tid + k * 256;
        int pxl = i >> 5, f2l = i & 31;
        float lo = outT[(2 * f2l) * OT_S + pxl];
        float hi = outT[(2 * f2l + 1) * OT_S + pxl];
        g_hb[(pb + pxl) * 128 + fcol + f2l] = packbf(lo, hi);
    }
}

// =====================================================================
// K4B: pw2 + bias + residual. M=64 c/block (of 128), N=128 px, K=256
// in 2 chunks. grid (256, 2), block 256, 3 CTAs/SM.
// =====================================================================
__global__ __launch_bounds__(256, 3) void k4b_pw2(
    const float* __restrict__ p2w, const float* __restrict__ p2b,
    const float* __restrict__ x,   float* __restrict__ out) {
    extern __shared__ unsigned smu[];
    unsigned* w2u = smu;                       // 64*68
    unsigned* hsu = smu + 64 * 68;             // 64*137
    float* b2s = (float*)(hsu + 64 * 137);     // 64
    float* outT = (float*)smu;                 // 64*130 (union)
    int tid = threadIdx.x;
    int c0 = blockIdx.y * 64;
    int pb = blockIdx.x * 128, b = pb >> 12, pin = pb & 4095;
    if (tid < 64) b2s[tid] = p2b[c0 + tid];

    int wid = tid >> 5, lane = tid & 31, gid = lane >> 2, ctid = lane & 3;
    int m = wid & 3, ng = wid >> 2;
    float acc[8][4];
#pragma unroll
    for (int nt = 0; nt < 8; nt++)
#pragma unroll
        for (int q = 0; q < 4; q++) acc[nt][q] = 0.f;

    for (int kc = 0; kc < 2; kc++) {
        __syncthreads();
#pragma unroll
        for (int k = 0; k < 16; k++) {
            int i = tid + k * 256;
            int c = i >> 6, f2 = i & 63;
            float2 wv = *(const float2*)(p2w + (c0 + c) * 256 + kc * 128 + 2 * f2);
            w2u[c * 68 + f2] = packbf(wv.x, wv.y);
        }
#pragma unroll
        for (int k = 0; k < 32; k++) {
            int i = tid + k * 256;
            int p = i >> 6, f2 = i & 63;
            hsu[f2 * 137 + p] = g_hb[(pb + p) * 128 + kc * 64 + f2];
        }
        __syncthreads();
#pragma unroll
        for (int s = 0; s < 8; s++) {
            const unsigned* ap = w2u + (m * 16 + gid) * 68 + s * 8 + ctid;
            unsigned a0 = ap[0], a1 = ap[8 * 68], a2 = ap[4], a3 = ap[8 * 68 + 4];
#pragma unroll
            for (int nt = 0; nt < 8; nt++) {
                int pxn = ng * 64 + nt * 8 + gid;
                unsigned b0 = hsu[(s * 8 + ctid) * 137 + pxn];
                unsigned b1v = hsu[(s * 8 + ctid + 4) * 137 + pxn];
                mma16(acc[nt], a0, a1, a2, a3, b0, b1v);
            }
        }
    }
    __syncthreads();   // staging dead → outT

    int crow = m * 16 + gid;
    float bb0 = b2s[crow], bb1 = b2s[crow + 8];
#pragma unroll
    for (int nt = 0; nt < 8; nt++) {
        int px = ng * 64 + nt * 8 + 2 * ctid;
        *(float2*)(outT + crow * OT_S + px) =
            make_float2(acc[nt][0] + bb0, acc[nt][1] + bb0);
        *(float2*)(outT + (crow + 8) * OT_S + px) =
            make_float2(acc[nt][2] + bb1, acc[nt][3] + bb1);
    }
    __syncthreads();

    // coalesced residual + store (NCHW): 64 c × 64 px-pairs = 4096 float2.
    // float2 (8B) stays aligned for every c with OT_S=130 (float4 would not).
#pragma unroll
    for (int k = 0; k < 16; k++) {
        int i = tid + k * 256;
        int c = i >> 6, p2 = (i & 63) * 2;
        float2 v = *(const float2*)(outT + c * OT_S + p2);
        int base = (b * DIM + c0 + c) * HW + pin + p2;
        float2 xi = *(const float2*)(x + base);
        *(float2*)(out + base) = make_float2(v.x + xi.x, v.y + xi.y);
    }
}

// =====================================================================
extern "C" void kernel_launch(void* const* d_in, const int* in_sizes, int n_in,
                              void* d_out, int out_size) {
    const float* x    = (const float*)d_in[0];
    const float* c1w  = (const float*)d_in[1];
    const float* c1b  = (const float*)d_in[2];
    const float* bng  = (const float*)d_in[3];
    const float* bnb  = (const float*)d_in[4];
    const float* bnm  = (const float*)d_in[5];
    const float* bnv  = (const float*)d_in[6];
    const float* c2w  = (const float*)d_in[7];
    const float* c2b  = (const float*)d_in[8];
    const float* lng  = (const float*)d_in[9];
    const float* lnb  = (const float*)d_in[10];
    const float* p1w  = (const float*)d_in[11];
    const float* p1b  = (const float*)d_in[12];
    const float* p2w  = (const float*)d_in[13];
    const float* p2b  = (const float*)d_in[14];
    float* out = (float*)d_out;

    const int SM_K1  = (32 * 68 + 64 * 136 + 64) * 4;
    const int SM_K23 = (49 * WGT_S + GC * XS_CH) * 4;
    const int SM_K4  = (64 * 68 + 64 * 137 + 64) * 4;     // 52.5 KB

    cudaFuncSetAttribute(k1_conv1,      cudaFuncAttributeMaxDynamicSharedMemorySize, SM_K1);
    cudaFuncSetAttribute(k23_conv2_inv, cudaFuncAttributeMaxDynamicSharedMemorySize, SM_K23);
    cudaFuncSetAttribute(k4a_pw1,       cudaFuncAttributeMaxDynamicSharedMemorySize, SM_K4);
    cudaFuncSetAttribute(k4b_pw2,       cudaFuncAttributeMaxDynamicSharedMemorySize, SM_K4);

    k1_conv1<<<256, 256, SM_K1>>>(x, c1w, c1b, bng, bnb, bnm, bnv);
    k23_conv2_inv<<<dim3(8, 8, 8), 256, SM_K23>>>(x, c2w, c2b);
    k4_ln<<<4096, 256>>>(lng, lnb);
    k4a_pw1<<<dim3(256, 4), 256, SM_K4>>>(p1w, p1b);
    k4b_pw2<<<dim3(256, 2), 256, SM_K4>>>(p2w, p2b, x, out);
}

// round 9
// speedup vs baseline: 1.3055x; 1.3055x over previous
#include <cuda_runtime.h>
#include <cuda_bf16.h>
#include <math.h>

// Problem constants
#define BB   8
#define DIM  128
#define HH   64
#define WW   64
#define HW   4096
#define KK   7
#define GG   8
#define GC   16
#define C1   32
#define C2   392
#define NPIX 32768

// -------- scratch (device globals) --------
__device__ float    g_t[BB * C1 * HW];        // conv1+bn+relu, NCHW fp32 (4 MB)
__device__ float    g_y[NPIX * DIM];          // involution out, NHWC fp32 (17 MB)
__device__ unsigned g_yn[NPIX * 64];          // LN out, bf16 k-pairs, [px][c/2] (8 MB)
__device__ unsigned g_hb[NPIX * 128];         // pw1+gelu out, bf16 k-pairs, [px][f/2] (16 MB)

// -------- helpers --------
__device__ __forceinline__ unsigned packbf(float lo, float hi) {
    unsigned r; asm("cvt.rn.bf16x2.f32 %0, %1, %2;" : "=r"(r) : "f"(hi), "f"(lo)); return r;
}
__device__ __forceinline__ void mma16(float* c, unsigned a0, unsigned a1,
                                      unsigned a2, unsigned a3,
                                      unsigned b0, unsigned b1) {
    asm volatile(
        "mma.sync.aligned.m16n8k16.row.col.f32.bf16.bf16.f32 "
        "{%0,%1,%2,%3}, {%4,%5,%6,%7}, {%8,%9}, {%0,%1,%2,%3};\n"
        : "+f"(c[0]), "+f"(c[1]), "+f"(c[2]), "+f"(c[3])
        : "r"(a0), "r"(a1), "r"(a2), "r"(a3), "r"(b0), "r"(b1));
}
__device__ __forceinline__ void ldsm4(unsigned& r0, unsigned& r1,
                                      unsigned& r2, unsigned& r3, unsigned addr) {
    asm volatile("ldmatrix.sync.aligned.m8n8.x4.shared.b16 {%0,%1,%2,%3}, [%4];\n"
        : "=r"(r0), "=r"(r1), "=r"(r2), "=r"(r3) : "r"(addr));
}
// tanh-form GELU (validated R8: rel_err unchanged at 1.79e-4)
__device__ __forceinline__ float gelu_fast(float z) {
    float u = z * (0.7978845608f + 0.0356774081f * z * z);
    float e = __expf(-2.f * u);
    return __fdividef(z, 1.f + e);
}

// Row stride for ldmatrix operand tiles: 64 k-pairs + 4 pad = 68 u32 = 272 B.
// Row r starts at bank 4r mod 32 → 8 rows × 16B cover all 32 banks.
#define RS 68
#define RSB 272

// =====================================================================
// K1: t = relu(bn(conv1(x)))  — bf16 MMA, M=32, N=128px, K=128
// =====================================================================
__global__ __launch_bounds__(256) void k1_conv1(
    const float* __restrict__ x,  const float* __restrict__ w1,
    const float* __restrict__ b1, const float* __restrict__ bng,
    const float* __restrict__ bnb, const float* __restrict__ bnm,
    const float* __restrict__ bnv) {
    extern __shared__ unsigned smu[];
    unsigned* wAu = smu;                 // 32*68
    unsigned* xsu = smu + 32 * 68;       // 64*136
    float* bs = (float*)(xsu + 64 * 136);
    float* ss = bs + 32;
    int tid = threadIdx.x;

    if (tid < 32) {
        float sc = bng[tid] * rsqrtf(bnv[tid] + 1e-5f);
        ss[tid] = sc;
        bs[tid] = b1[tid] * sc + bnb[tid] - bnm[tid] * sc;
    }
    __syncthreads();
    for (int i = tid; i < 32 * 64; i += 256) {
        int o = i >> 6, c2 = i & 63;
        float sc = ss[o];
        wAu[o * 68 + c2] = packbf(w1[o * 128 + 2 * c2] * sc, w1[o * 128 + 2 * c2 + 1] * sc);
    }
    int pb = blockIdx.x * 128, b = pb >> 12, pin = pb & 4095;
    const float* xb = x + b * DIM * HW + pin;
    for (int i = tid; i < 64 * 128; i += 256) {
        int c2 = i >> 7, p = i & 127;
        xsu[c2 * 136 + p] = packbf(xb[(2 * c2) * HW + p], xb[(2 * c2 + 1) * HW + p]);
    }
    __syncthreads();

    int wid = tid >> 5, lane = tid & 31, gid = lane >> 2, ctid = lane & 3;
    int m = wid & 1, ng = wid >> 1;
    int px0 = ng * 32;
    float acc[4][4];
#pragma unroll
    for (int a = 0; a < 4; a++)
#pragma unroll
        for (int q = 0; q < 4; q++) acc[a][q] = 0.f;

#pragma unroll
    for (int s = 0; s < 8; s++) {
        const unsigned* ap = wAu + (m * 16 + gid) * 68 + s * 8 + ctid;
        unsigned a0 = ap[0], a1 = ap[8 * 68], a2 = ap[4], a3 = ap[8 * 68 + 4];
#pragma unroll
        for (int nt = 0; nt < 4; nt++) {
            int pxn = px0 + nt * 8 + gid;
            unsigned b0 = xsu[(s * 8 + ctid) * 136 + pxn];
            unsigned b1v = xsu[(s * 8 + ctid + 4) * 136 + pxn];
            mma16(acc[nt], a0, a1, a2, a3, b0, b1v);
        }
    }
    float* tb = g_t + b * C1 * HW + pin;
    int o0 = m * 16 + gid;
#pragma unroll
    for (int nt = 0; nt < 4; nt++) {
        int px = px0 + nt * 8 + 2 * ctid;
        float b0v = bs[o0], b1v = bs[o0 + 8];
        *(float2*)(tb + o0 * HW + px) =
            make_float2(fmaxf(acc[nt][0] + b0v, 0.f), fmaxf(acc[nt][1] + b0v, 0.f));
        *(float2*)(tb + (o0 + 8) * HW + px) =
            make_float2(fmaxf(acc[nt][2] + b1v, 0.f), fmaxf(acc[nt][3] + b1v, 0.f));
    }
}

// =====================================================================
// K23: fused conv2 + involution (unchanged)
// =====================================================================
#define XS_ROW 72
#define XS_CH  (14 * 72)
#define WGT_S  520
__global__ __launch_bounds__(256) void k23_conv2_inv(
    const float* __restrict__ x, const float* __restrict__ w2,
    const float* __restrict__ b2) {
    extern __shared__ float smf[];
    float* wgt = smf;
    float* xs  = smf + 49 * WGT_S;
    unsigned* tsu = (unsigned*)xs;
    unsigned* wAu = tsu + 16 * WGT_S;
    float* bsm = (float*)(wAu + 64 * 20);
    int tid = threadIdx.x;
    int h0 = blockIdx.x * 8;
    int g  = blockIdx.y;
    int b  = blockIdx.z;

    const float* tb = g_t + b * C1 * HW + h0 * 64;
    for (int i = tid; i < 16 * 512; i += 256) {
        int c2 = i >> 9, px = i & 511;
        tsu[c2 * WGT_S + px] = packbf(tb[(2 * c2) * HW + px], tb[(2 * c2 + 1) * HW + px]);
    }
    for (int i = tid; i < 64 * 16; i += 256) {
        int o = i >> 4, c2 = i & 15;
        float a0 = 0.f, a1 = 0.f;
        if (o < 49) {
            int go = g * 49 + o;
            a0 = w2[go * C1 + 2 * c2];
            a1 = w2[go * C1 + 2 * c2 + 1];
        }
        wAu[o * 20 + c2] = packbf(a0, a1);
    }
    if (tid < 64) bsm[tid] = (tid < 49) ? b2[g * 49 + tid] : 0.f;
    __syncthreads();

    int wid = tid >> 5, lane = tid & 31, gid = lane >> 2, ctid = lane & 3;
    int m = wid & 3, ng = wid >> 2;
    int orow = m * 16 + gid;
    float bb0 = bsm[orow], bb1 = bsm[orow + 8];
#pragma unroll
    for (int nh = 0; nh < 2; nh++) {
        float acc[16][4];
#pragma unroll
        for (int nt = 0; nt < 16; nt++)
#pragma unroll
            for (int q = 0; q < 4; q++) acc[nt][q] = 0.f;
#pragma unroll
        for (int s = 0; s < 2; s++) {
            const unsigned* ap = wAu + orow * 20 + s * 8 + ctid;
            unsigned a0 = ap[0], a1 = ap[8 * 20], a2 = ap[4], a3 = ap[8 * 20 + 4];
#pragma unroll
            for (int nt = 0; nt < 16; nt++) {
                int pxn = nh * 256 + ng * 128 + nt * 8 + gid;
                unsigned b0 = tsu[(s * 8 + ctid) * WGT_S + pxn];
                unsigned b1v = tsu[(s * 8 + ctid + 4) * WGT_S + pxn];
                mma16(acc[nt], a0, a1, a2, a3, b0, b1v);
            }
        }
#pragma unroll
        for (int nt = 0; nt < 16; nt++) {
            int px = nh * 256 + ng * 128 + nt * 8 + 2 * ctid;
            if (orow < 49)
                *(float2*)(wgt + orow * WGT_S + px) =
                    make_float2(acc[nt][0] + bb0, acc[nt][1] + bb0);
            if (orow + 8 < 49)
                *(float2*)(wgt + (orow + 8) * WGT_S + px) =
                    make_float2(acc[nt][2] + bb1, acc[nt][3] + bb1);
        }
    }
    __syncthreads();

    for (int i = tid; i < GC * XS_CH; i += 256) xs[i] = 0.f;
    __syncthreads();
    const float* xg = x + (b * DIM + g * GC) * HW;
    for (int idx = tid; idx < GC * 14 * 64; idx += 256) {
        int gc = idx / (14 * 64);
        int rem = idx - gc * (14 * 64);
        int rr = rem >> 6, ww = rem & 63;
        int hh = h0 - 3 + rr;
        if (hh >= 0 && hh < HH)
            xs[gc * XS_CH + rr * XS_ROW + ww + 3] = xg[gc * HW + hh * WW + ww];
    }
    __syncthreads();

    int gcH = tid & 1;
    int pxq = tid >> 1;
    int r = pxq >> 4, w0 = (pxq & 15) * 4;
    float acc[8][4];
#pragma unroll
    for (int gc8 = 0; gc8 < 8; gc8++)
#pragma unroll
        for (int l = 0; l < 4; l++) acc[gc8][l] = 0.f;

    const float* wp = wgt + r * 64 + w0;
#pragma unroll
    for (int i = 0; i < KK; i++) {
        float4 wv[KK];
#pragma unroll
        for (int j = 0; j < KK; j++)
            wv[j] = *(const float4*)(wp + (i * KK + j) * WGT_S);
#pragma unroll
        for (int gc8 = 0; gc8 < 8; gc8++) {
            int gc = gcH * 8 + gc8;
            const float* xrow = xs + gc * XS_CH + (r + i) * XS_ROW + w0;
            float4 xa = *(const float4*)(xrow);
            float4 xb4 = *(const float4*)(xrow + 4);
            float4 xc = *(const float4*)(xrow + 8);
            float xw[12] = {xa.x, xa.y, xa.z, xa.w, xb4.x, xb4.y, xb4.z, xb4.w,
                            xc.x, xc.y, xc.z, xc.w};
#pragma unroll
            for (int j = 0; j < KK; j++) {
                acc[gc8][0] += wv[j].x * xw[j];
                acc[gc8][1] += wv[j].y * xw[j + 1];
                acc[gc8][2] += wv[j].z * xw[j + 2];
                acc[gc8][3] += wv[j].w * xw[j + 3];
            }
        }
    }
#pragma unroll
    for (int l = 0; l < 4; l++) {
        float* yo = g_y + (b * HW + (h0 + r) * WW + w0 + l) * DIM + g * GC + gcH * 8;
        *(float4*)(yo)     = make_float4(acc[0][l], acc[1][l], acc[2][l], acc[3][l]);
        *(float4*)(yo + 4) = make_float4(acc[4][l], acc[5][l], acc[6][l], acc[7][l]);
    }
}

// =====================================================================
// K4LN: LayerNorm, warp per pixel. g_yn layout [px][c/2].
// =====================================================================
__global__ __launch_bounds__(256) void k4_ln(
    const float* __restrict__ lng_g, const float* __restrict__ lnb_g) {
    __shared__ float lng[128], lnb[128];
    int tid = threadIdx.x;
    if (tid < 128) { lng[tid] = lng_g[tid]; lnb[tid] = lnb_g[tid]; }
    __syncthreads();

    int warp = tid >> 5, lane = tid & 31;
    int p = blockIdx.x * 8 + warp;
    float4 v = *(const float4*)(g_y + p * DIM + lane * 4);
    float s = v.x + v.y + v.z + v.w;
    float q = v.x*v.x + v.y*v.y + v.z*v.z + v.w*v.w;
#pragma unroll
    for (int off = 16; off; off >>= 1) {
        s += __shfl_xor_sync(0xffffffffu, s, off);
        q += __shfl_xor_sync(0xffffffffu, q, off);
    }
    float mu = s * (1.f / 128.f);
    float var = q * (1.f / 128.f) - mu * mu;
    float rs = rsqrtf(var + 1e-6f);
    int c = lane * 4;
    float n0 = (v.x - mu) * rs * lng[c+0] + lnb[c+0];
    float n1 = (v.y - mu) * rs * lng[c+1] + lnb[c+1];
    float n2 = (v.z - mu) * rs * lng[c+2] + lnb[c+2];
    float n3 = (v.w - mu) * rs * lng[c+3] + lnb[c+3];
    g_yn[p * 64 + lane * 2]     = packbf(n0, n1);
    g_yn[p * 64 + lane * 2 + 1] = packbf(n2, n3);
}

// =====================================================================
// K4A: pw1 + fast GELU — ldmatrix mainloop. M=128 f/block (of 256),
// N=128 px, K=128. grid (256,2), block 256, 2 CTAs/SM.
// smem: aT[128][68] + bT[128][68] u32 (rows k-contiguous); bias @17408;
//       outT[128][130] f32 unions the operand buffers.
// =====================================================================
#define OT_S 130
__global__ __launch_bounds__(256, 2) void k4a_pw1(
    const float* __restrict__ p1w, const float* __restrict__ p1b) {
    extern __shared__ unsigned smu[];
    unsigned* aT = smu;                        // 128*68 (weights, rows=f)
    unsigned* bT = smu + 128 * RS;             // 128*68 (y, rows=px)
    float* b1s = (float*)(smu + 2 * 128 * RS); // 128
    float* outT = (float*)smu;                 // 128*130 (union, < 17408 u32)
    int tid = threadIdx.x;
    int f0 = blockIdx.y * 128;
    int pb = blockIdx.x * 128;

#pragma unroll
    for (int k = 0; k < 32; k++) {
        int i = tid + k * 256;
        int f = i >> 6, c2 = i & 63;
        float2 wv = *(const float2*)(p1w + (f0 + f) * 128 + 2 * c2);
        aT[f * RS + c2] = packbf(wv.x, wv.y);
    }
    if (tid < 128) b1s[tid] = p1b[f0 + tid];
#pragma unroll
    for (int k = 0; k < 32; k++) {
        int i = tid + k * 256;
        int p = i >> 6, c2 = i & 63;
        bT[p * RS + c2] = g_yn[(pb + p) * 64 + c2];
    }
    __syncthreads();

    int wid = tid >> 5, lane = tid & 31;
    int m = wid & 3, ng = wid >> 2;
    // ldmatrix base addresses (byte, shared space)
    unsigned aBase = (unsigned)__cvta_generic_to_shared(aT)
                   + (m * 32 + (lane & 15)) * RSB + (lane & 16);
    unsigned bBase = (unsigned)__cvta_generic_to_shared(bT)
                   + (ng * 64 + (lane & 7) + ((lane & 16) >> 1)) * RSB
                   + ((lane & 8) << 1);
    float acc[2][8][4];
#pragma unroll
    for (int mt = 0; mt < 2; mt++)
#pragma unroll
        for (int nt = 0; nt < 8; nt++)
#pragma unroll
            for (int q = 0; q < 4; q++) acc[mt][nt][q] = 0.f;

#pragma unroll
    for (int s = 0; s < 8; s++) {
        unsigned a[2][4];
#pragma unroll
        for (int mt = 0; mt < 2; mt++)
            ldsm4(a[mt][0], a[mt][1], a[mt][2], a[mt][3],
                  aBase + mt * 16 * RSB + s * 32);
#pragma unroll
        for (int ntp = 0; ntp < 4; ntp++) {
            unsigned b0, b1v, b2, b3;
            ldsm4(b0, b1v, b2, b3, bBase + ntp * 16 * RSB + s * 32);
#pragma unroll
            for (int mt = 0; mt < 2; mt++) {
                mma16(acc[mt][2 * ntp],     a[mt][0], a[mt][1], a[mt][2], a[mt][3], b0, b1v);
                mma16(acc[mt][2 * ntp + 1], a[mt][0], a[mt][1], a[mt][2], a[mt][3], b2, b3);
            }
        }
    }
    __syncthreads();   // operand buffers dead → outT

    int gid = lane >> 2, ctid = lane & 3;
#pragma unroll
    for (int mt = 0; mt < 2; mt++) {
        int frow = m * 32 + mt * 16 + gid;
        float bb0 = b1s[frow], bb1 = b1s[frow + 8];
#pragma unroll
        for (int nt = 0; nt < 8; nt++) {
            int px = ng * 64 + nt * 8 + 2 * ctid;
            *(float2*)(outT + frow * OT_S + px) =
                make_float2(gelu_fast(acc[mt][nt][0] + bb0), gelu_fast(acc[mt][nt][1] + bb0));
            *(float2*)(outT + (frow + 8) * OT_S + px) =
                make_float2(gelu_fast(acc[mt][nt][2] + bb1), gelu_fast(acc[mt][nt][3] + bb1));
        }
    }
    __syncthreads();

    // coalesced pack + store to g_hb [px][f/2]
    int fcol = f0 >> 1;
#pragma unroll
    for (int k = 0; k < 32; k++) {
        int i = tid + k * 256;
        int pxl = i >> 6, f2l = i & 63;
        float lo = outT[(2 * f2l) * OT_S + pxl];
        float hi = outT[(2 * f2l + 1) * OT_S + pxl];
        g_hb[(pb + pxl) * 128 + fcol + f2l] = packbf(lo, hi);
    }
}

// =====================================================================
// K4B: pw2 + bias + residual — ldmatrix mainloop. M=128 c, N=128 px,
// K=256 in 2 chunks. grid 256, block 256, 2 CTAs/SM.
// =====================================================================
__global__ __launch_bounds__(256, 2) void k4b_pw2(
    const float* __restrict__ p2w, const float* __restrict__ p2b,
    const float* __restrict__ x,   float* __restrict__ out) {
    extern __shared__ unsigned smu[];
    unsigned* aT = smu;                        // 128*68 (w2, rows=c)
    unsigned* bT = smu + 128 * RS;             // 128*68 (h, rows=px)
    float* b2s = (float*)(smu + 2 * 128 * RS); // 128
    float* outT = (float*)smu;                 // 128*130 (union)
    int tid = threadIdx.x;
    int pb = blockIdx.x * 128, b = pb >> 12, pin = pb & 4095;
    if (tid < 128) b2s[tid] = p2b[tid];

    int wid = tid >> 5, lane = tid & 31;
    int m = wid & 3, ng = wid >> 2;
    unsigned aBase = (unsigned)__cvta_generic_to_shared(aT)
                   + (m * 32 + (lane & 15)) * RSB + (lane & 16);
    unsigned bBase = (unsigned)__cvta_generic_to_shared(bT)
                   + (ng * 64 + (lane & 7) + ((lane & 16) >> 1)) * RSB
                   + ((lane & 8) << 1);
    float acc[2][8][4];
#pragma unroll
    for (int mt = 0; mt < 2; mt++)
#pragma unroll
        for (int nt = 0; nt < 8; nt++)
#pragma unroll
            for (int q = 0; q < 4; q++) acc[mt][nt][q] = 0.f;

    for (int kc = 0; kc < 2; kc++) {
        __syncthreads();
#pragma unroll
        for (int k = 0; k < 32; k++) {
            int i = tid + k * 256;
            int c = i >> 6, f2 = i & 63;
            float2 wv = *(const float2*)(p2w + c * 256 + kc * 128 + 2 * f2);
            aT[c * RS + f2] = packbf(wv.x, wv.y);
        }
#pragma unroll
        for (int k = 0; k < 32; k++) {
            int i = tid + k * 256;
            int p = i >> 6, f2 = i & 63;
            bT[p * RS + f2] = g_hb[(pb + p) * 128 + kc * 64 + f2];
        }
        __syncthreads();
#pragma unroll
        for (int s = 0; s < 8; s++) {
            unsigned a[2][4];
#pragma unroll
            for (int mt = 0; mt < 2; mt++)
                ldsm4(a[mt][0], a[mt][1], a[mt][2], a[mt][3],
                      aBase + mt * 16 * RSB + s * 32);
#pragma unroll
            for (int ntp = 0; ntp < 4; ntp++) {
                unsigned b0, b1v, b2v, b3;
                ldsm4(b0, b1v, b2v, b3, bBase + ntp * 16 * RSB + s * 32);
#pragma unroll
                for (int mt = 0; mt < 2; mt++) {
                    mma16(acc[mt][2 * ntp],     a[mt][0], a[mt][1], a[mt][2], a[mt][3], b0, b1v);
                    mma16(acc[mt][2 * ntp + 1], a[mt][0], a[mt][1], a[mt][2], a[mt][3], b2v, b3);
                }
            }
        }
    }
    __syncthreads();   // operand buffers dead → outT

    int gid = lane >> 2, ctid = lane & 3;
#pragma unroll
    for (int mt = 0; mt < 2; mt++) {
        int crow = m * 32 + mt * 16 + gid;
        float bb0 = b2s[crow], bb1 = b2s[crow + 8];
#pragma unroll
        for (int nt = 0; nt < 8; nt++) {
            int px = ng * 64 + nt * 8 + 2 * ctid;
            *(float2*)(outT + crow * OT_S + px) =
                make_float2(acc[mt][nt][0] + bb0, acc[mt][nt][1] + bb0);
            *(float2*)(outT + (crow + 8) * OT_S + px) =
                make_float2(acc[mt][nt][2] + bb1, acc[mt][nt][3] + bb1);
        }
    }
    __syncthreads();

    // coalesced residual + store (NCHW): 128 c × 64 px-pairs = 8192 float2
#pragma unroll
    for (int k = 0; k < 32; k++) {
        int i = tid + k * 256;
        int c = i >> 6, p2 = (i & 63) * 2;
        float2 v = *(const float2*)(outT + c * OT_S + p2);
        int base = (b * DIM + c) * HW + pin + p2;
        float2 xi = *(const float2*)(x + base);
        *(float2*)(out + base) = make_float2(v.x + xi.x, v.y + xi.y);
    }
}

// =====================================================================
extern "C" void kernel_launch(void* const* d_in, const int* in_sizes, int n_in,
                              void* d_out, int out_size) {
    const float* x    = (const float*)d_in[0];
    const float* c1w  = (const float*)d_in[1];
    const float* c1b  = (const float*)d_in[2];
    const float* bng  = (const float*)d_in[3];
    const float* bnb  = (const float*)d_in[4];
    const float* bnm  = (const float*)d_in[5];
    const float* bnv  = (const float*)d_in[6];
    const float* c2w  = (const float*)d_in[7];
    const float* c2b  = (const float*)d_in[8];
    const float* lng  = (const float*)d_in[9];
    const float* lnb  = (const float*)d_in[10];
    const float* p1w  = (const float*)d_in[11];
    const float* p1b  = (const float*)d_in[12];
    const float* p2w  = (const float*)d_in[13];
    const float* p2b  = (const float*)d_in[14];
    float* out = (float*)d_out;

    const int SM_K1  = (32 * 68 + 64 * 136 + 64) * 4;
    const int SM_K23 = (49 * WGT_S + GC * XS_CH) * 4;
    const int SM_K4  = (2 * 128 * RS + 128) * 4;          // 70144 B

    cudaFuncSetAttribute(k1_conv1,      cudaFuncAttributeMaxDynamicSharedMemorySize, SM_K1);
    cudaFuncSetAttribute(k23_conv2_inv, cudaFuncAttributeMaxDynamicSharedMemorySize, SM_K23);
    cudaFuncSetAttribute(k4a_pw1,       cudaFuncAttributeMaxDynamicSharedMemorySize, SM_K4);
    cudaFuncSetAttribute(k4b_pw2,       cudaFuncAttributeMaxDynamicSharedMemorySize, SM_K4);

    k1_conv1<<<256, 256, SM_K1>>>(x, c1w, c1b, bng, bnb, bnm, bnv);
    k23_conv2_inv<<<dim3(8, 8, 8), 256, SM_K23>>>(x, c2w, c2b);
    k4_ln<<<4096, 256>>>(lng, lnb);
    k4a_pw1<<<dim3(256, 2), 256, SM_K4>>>(p1w, p1b);
    k4b_pw2<<<256, 256, SM_K4>>>(p2w, p2b, x, out);
}

// round 10
// speedup vs baseline: 1.3289x; 1.0179x over previous
#include <cuda_runtime.h>
#include <cuda_bf16.h>
#include <math.h>

// Problem constants
#define BB   8
#define DIM  128
#define HH   64
#define WW   64
#define HW   4096
#define KK   7
#define GG   8
#define GC   16
#define C1   32
#define C2   392
#define NPIX 32768

// -------- scratch (device globals) --------
__device__ float    g_t[BB * C1 * HW];        // conv1+bn+relu, NCHW fp32 (4 MB)
__device__ float    g_y[NPIX * DIM];          // involution out, NHWC fp32 (17 MB)
__device__ unsigned g_hb[NPIX * 128];         // pw1+gelu out, bf16 k-pairs, [px][f/2] (16 MB)

// -------- helpers --------
__device__ __forceinline__ unsigned packbf(float lo, float hi) {
    unsigned r; asm("cvt.rn.bf16x2.f32 %0, %1, %2;" : "=r"(r) : "f"(hi), "f"(lo)); return r;
}
__device__ __forceinline__ void mma16(float* c, unsigned a0, unsigned a1,
                                      unsigned a2, unsigned a3,
                                      unsigned b0, unsigned b1) {
    asm volatile(
        "mma.sync.aligned.m16n8k16.row.col.f32.bf16.bf16.f32 "
        "{%0,%1,%2,%3}, {%4,%5,%6,%7}, {%8,%9}, {%0,%1,%2,%3};\n"
        : "+f"(c[0]), "+f"(c[1]), "+f"(c[2]), "+f"(c[3])
        : "r"(a0), "r"(a1), "r"(a2), "r"(a3), "r"(b0), "r"(b1));
}
__device__ __forceinline__ void ldsm4(unsigned& r0, unsigned& r1,
                                      unsigned& r2, unsigned& r3, unsigned addr) {
    asm volatile("ldmatrix.sync.aligned.m8n8.x4.shared.b16 {%0,%1,%2,%3}, [%4];\n"
        : "=r"(r0), "=r"(r1), "=r"(r2), "=r"(r3) : "r"(addr));
}
// tanh-form GELU (validated: rel_err unchanged at 1.79e-4)
__device__ __forceinline__ float gelu_fast(float z) {
    float u = z * (0.7978845608f + 0.0356774081f * z * z);
    float e = __expf(-2.f * u);
    return __fdividef(z, 1.f + e);
}

// Row stride for ldmatrix operand tiles: 64 k-pairs + 4 pad = 68 u32 = 272 B.
#define RS 68
#define RSB 272

// =====================================================================
// K1: t = relu(bn(conv1(x)))  — bf16 MMA, M=32, N=128px, K=128
// =====================================================================
__global__ __launch_bounds__(256) void k1_conv1(
    const float* __restrict__ x,  const float* __restrict__ w1,
    const float* __restrict__ b1, const float* __restrict__ bng,
    const float* __restrict__ bnb, const float* __restrict__ bnm,
    const float* __restrict__ bnv) {
    extern __shared__ unsigned smu[];
    unsigned* wAu = smu;                 // 32*68
    unsigned* xsu = smu + 32 * 68;       // 64*136
    float* bs = (float*)(xsu + 64 * 136);
    float* ss = bs + 32;
    int tid = threadIdx.x;

    if (tid < 32) {
        float sc = bng[tid] * rsqrtf(bnv[tid] + 1e-5f);
        ss[tid] = sc;
        bs[tid] = b1[tid] * sc + bnb[tid] - bnm[tid] * sc;
    }
    __syncthreads();
    for (int i = tid; i < 32 * 64; i += 256) {
        int o = i >> 6, c2 = i & 63;
        float sc = ss[o];
        wAu[o * 68 + c2] = packbf(w1[o * 128 + 2 * c2] * sc, w1[o * 128 + 2 * c2 + 1] * sc);
    }
    int pb = blockIdx.x * 128, b = pb >> 12, pin = pb & 4095;
    const float* xb = x + b * DIM * HW + pin;
    for (int i = tid; i < 64 * 128; i += 256) {
        int c2 = i >> 7, p = i & 127;
        xsu[c2 * 136 + p] = packbf(xb[(2 * c2) * HW + p], xb[(2 * c2 + 1) * HW + p]);
    }
    __syncthreads();

    int wid = tid >> 5, lane = tid & 31, gid = lane >> 2, ctid = lane & 3;
    int m = wid & 1, ng = wid >> 1;
    int px0 = ng * 32;
    float acc[4][4];
#pragma unroll
    for (int a = 0; a < 4; a++)
#pragma unroll
        for (int q = 0; q < 4; q++) acc[a][q] = 0.f;

#pragma unroll
    for (int s = 0; s < 8; s++) {
        const unsigned* ap = wAu + (m * 16 + gid) * 68 + s * 8 + ctid;
        unsigned a0 = ap[0], a1 = ap[8 * 68], a2 = ap[4], a3 = ap[8 * 68 + 4];
#pragma unroll
        for (int nt = 0; nt < 4; nt++) {
            int pxn = px0 + nt * 8 + gid;
            unsigned b0 = xsu[(s * 8 + ctid) * 136 + pxn];
            unsigned b1v = xsu[(s * 8 + ctid + 4) * 136 + pxn];
            mma16(acc[nt], a0, a1, a2, a3, b0, b1v);
        }
    }
    float* tb = g_t + b * C1 * HW + pin;
    int o0 = m * 16 + gid;
#pragma unroll
    for (int nt = 0; nt < 4; nt++) {
        int px = px0 + nt * 8 + 2 * ctid;
        float b0v = bs[o0], b1v = bs[o0 + 8];
        *(float2*)(tb + o0 * HW + px) =
            make_float2(fmaxf(acc[nt][0] + b0v, 0.f), fmaxf(acc[nt][1] + b0v, 0.f));
        *(float2*)(tb + (o0 + 8) * HW + px) =
            make_float2(fmaxf(acc[nt][2] + b1v, 0.f), fmaxf(acc[nt][3] + b1v, 0.f));
    }
}

// =====================================================================
// K23: fused conv2 + involution (unchanged)
// =====================================================================
#define XS_ROW 72
#define XS_CH  (14 * 72)
#define WGT_S  520
__global__ __launch_bounds__(256) void k23_conv2_inv(
    const float* __restrict__ x, const float* __restrict__ w2,
    const float* __restrict__ b2) {
    extern __shared__ float smf[];
    float* wgt = smf;
    float* xs  = smf + 49 * WGT_S;
    unsigned* tsu = (unsigned*)xs;
    unsigned* wAu = tsu + 16 * WGT_S;
    float* bsm = (float*)(wAu + 64 * 20);
    int tid = threadIdx.x;
    int h0 = blockIdx.x * 8;
    int g  = blockIdx.y;
    int b  = blockIdx.z;

    const float* tb = g_t + b * C1 * HW + h0 * 64;
    for (int i = tid; i < 16 * 512; i += 256) {
        int c2 = i >> 9, px = i & 511;
        tsu[c2 * WGT_S + px] = packbf(tb[(2 * c2) * HW + px], tb[(2 * c2 + 1) * HW + px]);
    }
    for (int i = tid; i < 64 * 16; i += 256) {
        int o = i >> 4, c2 = i & 15;
        float a0 = 0.f, a1 = 0.f;
        if (o < 49) {
            int go = g * 49 + o;
            a0 = w2[go * C1 + 2 * c2];
            a1 = w2[go * C1 + 2 * c2 + 1];
        }
        wAu[o * 20 + c2] = packbf(a0, a1);
    }
    if (tid < 64) bsm[tid] = (tid < 49) ? b2[g * 49 + tid] : 0.f;
    __syncthreads();

    int wid = tid >> 5, lane = tid & 31, gid = lane >> 2, ctid = lane & 3;
    int m = wid & 3, ng = wid >> 2;
    int orow = m * 16 + gid;
    float bb0 = bsm[orow], bb1 = bsm[orow + 8];
#pragma unroll
    for (int nh = 0; nh < 2; nh++) {
        float acc[16][4];
#pragma unroll
        for (int nt = 0; nt < 16; nt++)
#pragma unroll
            for (int q = 0; q < 4; q++) acc[nt][q] = 0.f;
#pragma unroll
        for (int s = 0; s < 2; s++) {
            const unsigned* ap = wAu + orow * 20 + s * 8 + ctid;
            unsigned a0 = ap[0], a1 = ap[8 * 20], a2 = ap[4], a3 = ap[8 * 20 + 4];
#pragma unroll
            for (int nt = 0; nt < 16; nt++) {
                int pxn = nh * 256 + ng * 128 + nt * 8 + gid;
                unsigned b0 = tsu[(s * 8 + ctid) * WGT_S + pxn];
                unsigned b1v = tsu[(s * 8 + ctid + 4) * WGT_S + pxn];
                mma16(acc[nt], a0, a1, a2, a3, b0, b1v);
            }
        }
#pragma unroll
        for (int nt = 0; nt < 16; nt++) {
            int px = nh * 256 + ng * 128 + nt * 8 + 2 * ctid;
            if (orow < 49)
                *(float2*)(wgt + orow * WGT_S + px) =
                    make_float2(acc[nt][0] + bb0, acc[nt][1] + bb0);
            if (orow + 8 < 49)
                *(float2*)(wgt + (orow + 8) * WGT_S + px) =
                    make_float2(acc[nt][2] + bb1, acc[nt][3] + bb1);
        }
    }
    __syncthreads();

    for (int i = tid; i < GC * XS_CH; i += 256) xs[i] = 0.f;
    __syncthreads();
    const float* xg = x + (b * DIM + g * GC) * HW;
    for (int idx = tid; idx < GC * 14 * 64; idx += 256) {
        int gc = idx / (14 * 64);
        int rem = idx - gc * (14 * 64);
        int rr = rem >> 6, ww = rem & 63;
        int hh = h0 - 3 + rr;
        if (hh >= 0 && hh < HH)
            xs[gc * XS_CH + rr * XS_ROW + ww + 3] = xg[gc * HW + hh * WW + ww];
    }
    __syncthreads();

    int gcH = tid & 1;
    int pxq = tid >> 1;
    int r = pxq >> 4, w0 = (pxq & 15) * 4;
    float acc[8][4];
#pragma unroll
    for (int gc8 = 0; gc8 < 8; gc8++)
#pragma unroll
        for (int l = 0; l < 4; l++) acc[gc8][l] = 0.f;

    const float* wp = wgt + r * 64 + w0;
#pragma unroll
    for (int i = 0; i < KK; i++) {
        float4 wv[KK];
#pragma unroll
        for (int j = 0; j < KK; j++)
            wv[j] = *(const float4*)(wp + (i * KK + j) * WGT_S);
#pragma unroll
        for (int gc8 = 0; gc8 < 8; gc8++) {
            int gc = gcH * 8 + gc8;
            const float* xrow = xs + gc * XS_CH + (r + i) * XS_ROW + w0;
            float4 xa = *(const float4*)(xrow);
            float4 xb4 = *(const float4*)(xrow + 4);
            float4 xc = *(const float4*)(xrow + 8);
            float xw[12] = {xa.x, xa.y, xa.z, xa.w, xb4.x, xb4.y, xb4.z, xb4.w,
                            xc.x, xc.y, xc.z, xc.w};
#pragma unroll
            for (int j = 0; j < KK; j++) {
                acc[gc8][0] += wv[j].x * xw[j];
                acc[gc8][1] += wv[j].y * xw[j + 1];
                acc[gc8][2] += wv[j].z * xw[j + 2];
                acc[gc8][3] += wv[j].w * xw[j + 3];
            }
        }
    }
#pragma unroll
    for (int l = 0; l < 4; l++) {
        float* yo = g_y + (b * HW + (h0 + r) * WW + w0 + l) * DIM + g * GC + gcH * 8;
        *(float4*)(yo)     = make_float4(acc[0][l], acc[1][l], acc[2][l], acc[3][l]);
        *(float4*)(yo + 4) = make_float4(acc[4][l], acc[5][l], acc[6][l], acc[7][l]);
    }
}

// =====================================================================
// K4A: fused LN + pw1 + fast GELU — ldmatrix mainloop.
// M=128 f/block (of 256), N=128 px, K=128. grid (256,2), 256 thr, 2 CTAs/SM.
// LN computed in-block (2 thr/px) and packed straight into bT rows.
// =====================================================================
#define OT_S 130
__global__ __launch_bounds__(256, 2) void k4a_pw1(
    const float* __restrict__ p1w, const float* __restrict__ p1b,
    const float* __restrict__ lng_g, const float* __restrict__ lnb_g) {
    extern __shared__ unsigned smu[];
    unsigned* aT = smu;                        // 128*68 (weights, rows=f)
    unsigned* bT = smu + 128 * RS;             // 128*68 (LN(y), rows=px)
    float* b1s = (float*)(smu + 2 * 128 * RS); // 128
    float* lng = b1s + 128;                    // 128
    float* lnb = lng + 128;                    // 128
    float* outT = (float*)smu;                 // 128*130 (union, < 17408 u32)
    int tid = threadIdx.x;
    int f0 = blockIdx.y * 128;
    int pb = blockIdx.x * 128;

    // weight staging + params
#pragma unroll
    for (int k = 0; k < 32; k++) {
        int i = tid + k * 256;
        int f = i >> 6, c2 = i & 63;
        float2 wv = *(const float2*)(p1w + (f0 + f) * 128 + 2 * c2);
        aT[f * RS + c2] = packbf(wv.x, wv.y);
    }
    if (tid < 128) {
        b1s[tid] = p1b[f0 + tid];
        lng[tid] = lng_g[tid];
        lnb[tid] = lnb_g[tid];
    }
    __syncthreads();   // lng/lnb visible

    // ---- fused LayerNorm: 2 threads / pixel, pack into bT ----
    {
        int p = tid >> 1, half = tid & 1;
        const float* yp = g_y + (pb + p) * DIM + half * 64;
        float4 v[16];
        float s = 0.f, q = 0.f;
#pragma unroll
        for (int i = 0; i < 16; i++) {
            v[i] = *(const float4*)(yp + i * 4);
            s += v[i].x + v[i].y + v[i].z + v[i].w;
            q += v[i].x*v[i].x + v[i].y*v[i].y + v[i].z*v[i].z + v[i].w*v[i].w;
        }
        s += __shfl_xor_sync(0xffffffffu, s, 1);
        q += __shfl_xor_sync(0xffffffffu, q, 1);
        float mu = s * (1.f / 128.f);
        float var = q * (1.f / 128.f) - mu * mu;
        float rs = rsqrtf(var + 1e-6f);
        unsigned* brow = bT + p * RS + half * 32;
#pragma unroll
        for (int i = 0; i < 16; i++) {
            int c = half * 64 + i * 4;
            float n0 = (v[i].x - mu) * rs * lng[c+0] + lnb[c+0];
            float n1 = (v[i].y - mu) * rs * lng[c+1] + lnb[c+1];
            float n2 = (v[i].z - mu) * rs * lng[c+2] + lnb[c+2];
            float n3 = (v[i].w - mu) * rs * lng[c+3] + lnb[c+3];
            brow[2 * i]     = packbf(n0, n1);
            brow[2 * i + 1] = packbf(n2, n3);
        }
    }
    __syncthreads();

    int wid = tid >> 5, lane = tid & 31;
    int m = wid & 3, ng = wid >> 2;
    unsigned aBase = (unsigned)__cvta_generic_to_shared(aT)
                   + (m * 32 + (lane & 15)) * RSB + (lane & 16);
    unsigned bBase = (unsigned)__cvta_generic_to_shared(bT)
                   + (ng * 64 + (lane & 7) + ((lane & 16) >> 1)) * RSB
                   + ((lane & 8) << 1);
    float acc[2][8][4];
#pragma unroll
    for (int mt = 0; mt < 2; mt++)
#pragma unroll
        for (int nt = 0; nt < 8; nt++)
#pragma unroll
            for (int q = 0; q < 4; q++) acc[mt][nt][q] = 0.f;

#pragma unroll
    for (int s = 0; s < 8; s++) {
        unsigned a[2][4];
#pragma unroll
        for (int mt = 0; mt < 2; mt++)
            ldsm4(a[mt][0], a[mt][1], a[mt][2], a[mt][3],
                  aBase + mt * 16 * RSB + s * 32);
#pragma unroll
        for (int ntp = 0; ntp < 4; ntp++) {
            unsigned b0, b1v, b2, b3;
            ldsm4(b0, b1v, b2, b3, bBase + ntp * 16 * RSB + s * 32);
#pragma unroll
            for (int mt = 0; mt < 2; mt++) {
                mma16(acc[mt][2 * ntp],     a[mt][0], a[mt][1], a[mt][2], a[mt][3], b0, b1v);
                mma16(acc[mt][2 * ntp + 1], a[mt][0], a[mt][1], a[mt][2], a[mt][3], b2, b3);
            }
        }
    }
    __syncthreads();   // operand buffers dead → outT

    int gid = lane >> 2, ctid = lane & 3;
#pragma unroll
    for (int mt = 0; mt < 2; mt++) {
        int frow = m * 32 + mt * 16 + gid;
        float bb0 = b1s[frow], bb1 = b1s[frow + 8];
#pragma unroll
        for (int nt = 0; nt < 8; nt++) {
            int px = ng * 64 + nt * 8 + 2 * ctid;
            *(float2*)(outT + frow * OT_S + px) =
                make_float2(gelu_fast(acc[mt][nt][0] + bb0), gelu_fast(acc[mt][nt][1] + bb0));
            *(float2*)(outT + (frow + 8) * OT_S + px) =
                make_float2(gelu_fast(acc[mt][nt][2] + bb1), gelu_fast(acc[mt][nt][3] + bb1));
        }
    }
    __syncthreads();

    // coalesced pack + store to g_hb [px][f/2]
    int fcol = f0 >> 1;
#pragma unroll
    for (int k = 0; k < 32; k++) {
        int i = tid + k * 256;
        int pxl = i >> 6, f2l = i & 63;
        float lo = outT[(2 * f2l) * OT_S + pxl];
        float hi = outT[(2 * f2l + 1) * OT_S + pxl];
        g_hb[(pb + pxl) * 128 + fcol + f2l] = packbf(lo, hi);
    }
}

// =====================================================================
// K4B: pw2 + bias + residual — ldmatrix mainloop. M=128 c, N=128 px,
// K=256 in 2 chunks. grid 256, block 256, 2 CTAs/SM.
// =====================================================================
__global__ __launch_bounds__(256, 2) void k4b_pw2(
    const float* __restrict__ p2w, const float* __restrict__ p2b,
    const float* __restrict__ x,   float* __restrict__ out) {
    extern __shared__ unsigned smu[];
    unsigned* aT = smu;                        // 128*68 (w2, rows=c)
    unsigned* bT = smu + 128 * RS;             // 128*68 (h, rows=px)
    float* b2s = (float*)(smu + 2 * 128 * RS); // 128
    float* outT = (float*)smu;                 // 128*130 (union)
    int tid = threadIdx.x;
    int pb = blockIdx.x * 128, b = pb >> 12, pin = pb & 4095;
    if (tid < 128) b2s[tid] = p2b[tid];

    int wid = tid >> 5, lane = tid & 31;
    int m = wid & 3, ng = wid >> 2;
    unsigned aBase = (unsigned)__cvta_generic_to_shared(aT)
                   + (m * 32 + (lane & 15)) * RSB + (lane & 16);
    unsigned bBase = (unsigned)__cvta_generic_to_shared(bT)
                   + (ng * 64 + (lane & 7) + ((lane & 16) >> 1)) * RSB
                   + ((lane & 8) << 1);
    float acc[2][8][4];
#pragma unroll
    for (int mt = 0; mt < 2; mt++)
#pragma unroll
        for (int nt = 0; nt < 8; nt++)
#pragma unroll
            for (int q = 0; q < 4; q++) acc[mt][nt][q] = 0.f;

    for (int kc = 0; kc < 2; kc++) {
        __syncthreads();
#pragma unroll
        for (int k = 0; k < 32; k++) {
            int i = tid + k * 256;
            int c = i >> 6, f2 = i & 63;
            float2 wv = *(const float2*)(p2w + c * 256 + kc * 128 + 2 * f2);
            aT[c * RS + f2] = packbf(wv.x, wv.y);
        }
#pragma unroll
        for (int k = 0; k < 32; k++) {
            int i = tid + k * 256;
            int p = i >> 6, f2 = i & 63;
            bT[p * RS + f2] = g_hb[(pb + p) * 128 + kc * 64 + f2];
        }
        __syncthreads();
#pragma unroll
        for (int s = 0; s < 8; s++) {
            unsigned a[2][4];
#pragma unroll
            for (int mt = 0; mt < 2; mt++)
                ldsm4(a[mt][0], a[mt][1], a[mt][2], a[mt][3],
                      aBase + mt * 16 * RSB + s * 32);
#pragma unroll
            for (int ntp = 0; ntp < 4; ntp++) {
                unsigned b0, b1v, b2v, b3;
                ldsm4(b0, b1v, b2v, b3, bBase + ntp * 16 * RSB + s * 32);
#pragma unroll
                for (int mt = 0; mt < 2; mt++) {
                    mma16(acc[mt][2 * ntp],     a[mt][0], a[mt][1], a[mt][2], a[mt][3], b0, b1v);
                    mma16(acc[mt][2 * ntp + 1], a[mt][0], a[mt][1], a[mt][2], a[mt][3], b2v, b3);
                }
            }
        }
    }
    __syncthreads();   // operand buffers dead → outT

    int gid = lane >> 2, ctid = lane & 3;
#pragma unroll
    for (int mt = 0; mt < 2; mt++) {
        int crow = m * 32 + mt * 16 + gid;
        float bb0 = b2s[crow], bb1 = b2s[crow + 8];
#pragma unroll
        for (int nt = 0; nt < 8; nt++) {
            int px = ng * 64 + nt * 8 + 2 * ctid;
            *(float2*)(outT + crow * OT_S + px) =
                make_float2(acc[mt][nt][0] + bb0, acc[mt][nt][1] + bb0);
            *(float2*)(outT + (crow + 8) * OT_S + px) =
                make_float2(acc[mt][nt][2] + bb1, acc[mt][nt][3] + bb1);
        }
    }
    __syncthreads();

    // coalesced residual + store (NCHW): 128 c × 64 px-pairs = 8192 float2
#pragma unroll
    for (int k = 0; k < 32; k++) {
        int i = tid + k * 256;
        int c = i >> 6, p2 = (i & 63) * 2;
        float2 v = *(const float2*)(outT + c * OT_S + p2);
        int base = (b * DIM + c) * HW + pin + p2;
        float2 xi = *(const float2*)(x + base);
        *(float2*)(out + base) = make_float2(v.x + xi.x, v.y + xi.y);
    }
}

// =====================================================================
extern "C" void kernel_launch(void* const* d_in, const int* in_sizes, int n_in,
                              void* d_out, int out_size) {
    const float* x    = (const float*)d_in[0];
    const float* c1w  = (const float*)d_in[1];
    const float* c1b  = (const float*)d_in[2];
    const float* bng  = (const float*)d_in[3];
    const float* bnb  = (const float*)d_in[4];
    const float* bnm  = (const float*)d_in[5];
    const float* bnv  = (const float*)d_in[6];
    const float* c2w  = (const float*)d_in[7];
    const float* c2b  = (const float*)d_in[8];
    const float* lng  = (const float*)d_in[9];
    const float* lnb  = (const float*)d_in[10];
    const float* p1w  = (const float*)d_in[11];
    const float* p1b  = (const float*)d_in[12];
    const float* p2w  = (const float*)d_in[13];
    const float* p2b  = (const float*)d_in[14];
    float* out = (float*)d_out;

    const int SM_K1  = (32 * 68 + 64 * 136 + 64) * 4;
    const int SM_K23 = (49 * WGT_S + GC * XS_CH) * 4;
    const int SM_K4A = (2 * 128 * RS + 384) * 4;          // 71168 B
    const int SM_K4B = (2 * 128 * RS + 128) * 4;          // 70144 B

    cudaFuncSetAttribute(k1_conv1,      cudaFuncAttributeMaxDynamicSharedMemorySize, SM_K1);
    cudaFuncSetAttribute(k23_conv2_inv, cudaFuncAttributeMaxDynamicSharedMemorySize, SM_K23);
    cudaFuncSetAttribute(k4a_pw1,       cudaFuncAttributeMaxDynamicSharedMemorySize, SM_K4A);
    cudaFuncSetAttribute(k4b_pw2,       cudaFuncAttributeMaxDynamicSharedMemorySize, SM_K4B);

    k1_conv1<<<256, 256, SM_K1>>>(x, c1w, c1b, bng, bnb, bnm, bnv);
    k23_conv2_inv<<<dim3(8, 8, 8), 256, SM_K23>>>(x, c2w, c2b);
    k4a_pw1<<<dim3(256, 2), 256, SM_K4A>>>(p1w, p1b, lng, lnb);
    k4b_pw2<<<256, 256, SM_K4B>>>(p2w, p2b, x, out);
}